// round 2
// baseline (speedup 1.0000x reference)
#include <cuda_runtime.h>
#include <cstdint>

#define EMB 64
#define MAXN 200000
#define MAXB 16384

// Scratch (static __device__ globals: allocation-free, zero-init at module load).
__device__ float  g_hacc[2][(size_t)MAXN * EMB];    // sum of exp(e)*src_feat per dst node
__device__ float2 g_ds[2][MAXN];                    // .x = s_dst score, .y = sum of exp(e)
__device__ unsigned char g_flag[2][MAXN];           // 1 if node is in the batch
__device__ float  g_z[2][(size_t)MAXB * 2 * EMB];   // cat(relu(self), relu(neighbor))

// ---------------------------------------------------------------------------
// K1: per (side, batch element): mark flag, zero accumulators, compute s_dst.
// One warp per (side, b). Duplicate ids write identical values (benign).
// ---------------------------------------------------------------------------
__global__ void prep_kernel(const float* __restrict__ utab, const float* __restrict__ itab,
                            const float* __restrict__ Wa_u, const float* __restrict__ Wa_i,
                            const int* __restrict__ uids, const int* __restrict__ iids, int B)
{
    int gw = (blockIdx.x * blockDim.x + threadIdx.x) >> 5;
    int lane = threadIdx.x & 31;
    if (gw >= 2 * B) return;
    int side = gw >= B ? 1 : 0;
    int b = side ? gw - B : gw;
    int id = side ? iids[b] : uids[b];
    const float* tab = side ? itab : utab;
    const float* wa = (side ? Wa_i : Wa_u) + EMB;   // dst half of attention vector

    float2 v = *(const float2*)(tab + (size_t)id * EMB + 2 * lane);
    float p = v.x * wa[2 * lane] + v.y * wa[2 * lane + 1];
    #pragma unroll
    for (int o = 16; o; o >>= 1) p += __shfl_xor_sync(0xffffffffu, p, o);

    *(float2*)(&g_hacc[side][(size_t)id * EMB + 2 * lane]) = make_float2(0.f, 0.f);
    if (lane == 0) {
        g_ds[side][id] = make_float2(p, 0.f);
        g_flag[side][id] = 1;
    }
}

// ---------------------------------------------------------------------------
// K2: single fused edge pass (filter + score + exp + weighted scatter).
// 32 edges per warp; flagged edges (~8%) processed warp-cooperatively.
// blockIdx.y selects side (0: item->user agg, 1: user->item agg).
// No segment-max subtraction: logit std ~0.1, exp() is well-conditioned and
// the constant factor cancels in alpha = ex/den.
// ---------------------------------------------------------------------------
__global__ void edge_kernel(const float* __restrict__ utab, const float* __restrict__ itab,
                            const float* __restrict__ Wa_u, const float* __restrict__ Wa_i,
                            const int* __restrict__ src_iu, const int* __restrict__ dst_iu,
                            const int* __restrict__ src_ui, const int* __restrict__ dst_ui,
                            int E)
{
    int side = blockIdx.y;
    const float* stab = side ? utab : itab;         // source-node feature table
    const float* wa = side ? Wa_i : Wa_u;           // src half [0:64)
    const int* src = side ? src_ui : src_iu;
    const int* dst = side ? dst_ui : dst_iu;
    const unsigned char* flag = g_flag[side];

    int lane = threadIdx.x & 31;
    float wx = wa[2 * lane], wy = wa[2 * lane + 1];

    int warp = (blockIdx.x * blockDim.x + threadIdx.x) >> 5;
    int idx = warp * 32 + lane;

    int d = 0, s = 0, f = 0;
    if (idx < E) {
        d = dst[idx];
        f = flag[d];
        s = src[idx];
    }
    unsigned m = __ballot_sync(0xffffffffu, f);

    while (m) {
        int j = __ffs(m) - 1; m &= m - 1;
        int ds = __shfl_sync(0xffffffffu, d, j);
        int ss = __shfl_sync(0xffffffffu, s, j);

        // Warp-cooperative gather of the 64-float source row (256B, coalesced).
        float2 v = *(const float2*)(stab + (size_t)ss * EMB + 2 * lane);
        float p = v.x * wx + v.y * wy;
        #pragma unroll
        for (int o = 16; o; o >>= 1) p += __shfl_xor_sync(0xffffffffu, p, o);

        float e = p + g_ds[side][ds].x;
        e = e >= 0.f ? e : 0.01f * e;          // leaky_relu(., 0.01)
        float ex = __expf(e);

        if (lane == 0) atomicAdd(&g_ds[side][ds].y, ex);
        float* hp = &g_hacc[side][(size_t)ds * EMB + 2 * lane];
        atomicAdd(hp,     v.x * ex);
        atomicAdd(hp + 1, v.y * ex);
    }
}

// ---------------------------------------------------------------------------
// K3a: z = cat(relu(Ws@emb + bs), relu(Wn@h + bn)) per batch row.
// 64 rows per block; weights transposed into smem (stride 65, conflict-free).
// ---------------------------------------------------------------------------
__global__ void mlp1_kernel(const float* __restrict__ utab, const float* __restrict__ itab,
                            const float* __restrict__ Ws_u, const float* __restrict__ bs_u,
                            const float* __restrict__ Ws_i, const float* __restrict__ bs_i,
                            const float* __restrict__ Wn_u, const float* __restrict__ bn_u,
                            const float* __restrict__ Wn_i, const float* __restrict__ bn_i,
                            const int* __restrict__ uids, const int* __restrict__ iids, int B)
{
    int side = blockIdx.y;
    const float* tab = side ? itab : utab;
    const float* Ws = side ? Ws_i : Ws_u;
    const float* bsv = side ? bs_i : bs_u;
    const float* Wn = side ? Wn_i : Wn_u;
    const float* bnv = side ? bn_i : bn_u;
    const int* ids = side ? iids : uids;

    __shared__ float WsT[64 * 65];
    __shared__ float WnT[64 * 65];
    __shared__ float vec[4][2 * EMB];

    for (int t = threadIdx.x; t < 64 * 64; t += blockDim.x) {
        int x = t >> 6, k = t & 63;
        WsT[k * 65 + x] = Ws[t];
        WnT[k * 65 + x] = Wn[t];
    }
    __syncthreads();

    int x = threadIdx.x & 63;
    int ty = threadIdx.x >> 6;
    float bS = bsv[x], bN = bnv[x];

    for (int r0 = 0; r0 < 64; r0 += 4) {
        int b = blockIdx.x * 64 + r0 + ty;
        if (b >= B) b = 0;   // duplicate row 0: identical values, benign
        int id = ids[b];
        vec[ty][x] = tab[(size_t)id * EMB + x];
        float den = g_ds[side][id].y;
        float rden = den > 0.f ? 1.f / den : 0.f;   // empty segment -> h = 0
        vec[ty][EMB + x] = g_hacc[side][(size_t)id * EMB + x] * rden;
        __syncthreads();

        float a1 = bS, a2 = bN;
        #pragma unroll
        for (int k = 0; k < 64; k++) {
            a1 += WsT[k * 65 + x] * vec[ty][k];
            a2 += WnT[k * 65 + x] * vec[ty][EMB + k];
        }
        a1 = fmaxf(a1, 0.f); a2 = fmaxf(a2, 0.f);
        float* zr = &g_z[side][(size_t)b * 2 * EMB];
        zr[x] = a1;
        zr[EMB + x] = a2;
        __syncthreads();
    }
}

// ---------------------------------------------------------------------------
// K3b: out[:, side*64 + x] = relu(Wfc @ z)
// ---------------------------------------------------------------------------
__global__ void mlp2_kernel(const float* __restrict__ Wfc_u, const float* __restrict__ Wfc_i,
                            float* __restrict__ out, int B)
{
    int side = blockIdx.y;
    const float* W = side ? Wfc_i : Wfc_u;   // [64][128] row-major

    __shared__ float WT[128 * 65];
    __shared__ float vec[4][2 * EMB];

    for (int t = threadIdx.x; t < 64 * 128; t += blockDim.x) {
        int x = t >> 7, k = t & 127;
        WT[k * 65 + x] = W[t];
    }
    __syncthreads();

    int x = threadIdx.x & 63;
    int ty = threadIdx.x >> 6;

    for (int r0 = 0; r0 < 64; r0 += 4) {
        int b = blockIdx.x * 64 + r0 + ty;
        if (b >= B) b = 0;
        const float* zr = &g_z[side][(size_t)b * 2 * EMB];
        vec[ty][x] = zr[x];
        vec[ty][EMB + x] = zr[EMB + x];
        __syncthreads();

        float a = 0.f;
        #pragma unroll
        for (int k = 0; k < 128; k++) a += WT[k * 65 + x] * vec[ty][k];
        out[(size_t)b * 2 * EMB + side * EMB + x] = fmaxf(a, 0.f);
        __syncthreads();
    }
}

// ---------------------------------------------------------------------------
extern "C" void kernel_launch(void* const* d_in, const int* in_sizes, int n_in,
                              void* d_out, int out_size)
{
    const float* user_emb = (const float*)d_in[0];
    const float* item_emb = (const float*)d_in[1];
    const float* Wa_u = (const float*)d_in[2];
    const float* Wa_i = (const float*)d_in[3];
    const float* Wfc_u = (const float*)d_in[4];
    const float* Wfc_i = (const float*)d_in[5];
    const float* Ws_u = (const float*)d_in[6];
    const float* bs_u = (const float*)d_in[7];
    const float* Ws_i = (const float*)d_in[8];
    const float* bs_i = (const float*)d_in[9];
    const float* Wn_u = (const float*)d_in[10];
    const float* bn_u = (const float*)d_in[11];
    const float* Wn_i = (const float*)d_in[12];
    const float* bn_i = (const float*)d_in[13];
    const int* u      = (const int*)d_in[14];
    const int* ii     = (const int*)d_in[15];
    const int* src_iu = (const int*)d_in[16];
    const int* dst_iu = (const int*)d_in[17];
    const int* src_ui = (const int*)d_in[18];
    const int* dst_ui = (const int*)d_in[19];
    int B = in_sizes[14];
    int E = in_sizes[16];
    float* out = (float*)d_out;

    {   // K1: mark + zero + dst scores. One warp per (side, b).
        int threads = 256;
        int blocks = (2 * B * 32 + threads - 1) / threads;
        prep_kernel<<<blocks, threads>>>(user_emb, item_emb, Wa_u, Wa_i, u, ii, B);
    }
    {   // K2: fused filtered edge pass, both sides concurrent via gridDim.y.
        int threads = 256;
        int blocks = (E + 8 * 32 - 1) / (8 * 32);
        dim3 g(blocks, 2);
        edge_kernel<<<g, threads>>>(user_emb, item_emb, Wa_u, Wa_i,
                                    src_iu, dst_iu, src_ui, dst_ui, E);
    }
    {   // K3: batched dense MLPs.
        dim3 g((B + 63) / 64, 2);
        mlp1_kernel<<<g, 256>>>(user_emb, item_emb, Ws_u, bs_u, Ws_i, bs_i,
                                Wn_u, bn_u, Wn_i, bn_i, u, ii, B);
        mlp2_kernel<<<g, 256>>>(Wfc_u, Wfc_i, out, B);
    }
}

// round 5
// speedup vs baseline: 1.6667x; 1.6667x over previous
#include <cuda_runtime.h>
#include <cstdint>

#define EMB 64
#define MAXN 200000
#define MAXB 16384

// Scratch (static __device__ globals: allocation-free).
__device__ float  g_hacc[2][(size_t)MAXN * EMB];    // sum of exp(e)*src_feat per dst node
__device__ float2 g_ds[2][MAXN];                    // .x = s_dst score, .y = sum of exp(e)
__device__ unsigned char g_flag[2][MAXN];           // 1 if node is in the batch
__device__ float  g_z[2][(size_t)MAXB * 2 * EMB];   // cat(relu(self), relu(neighbor))

// ---------------------------------------------------------------------------
// K1: per (side, batch element): mark flag, zero accumulators, compute s_dst.
// One warp per (side, b). Duplicate ids write identical values (benign).
// ---------------------------------------------------------------------------
__global__ void __launch_bounds__(256)
prep_kernel(const float* __restrict__ utab, const float* __restrict__ itab,
            const float* __restrict__ Wa_u, const float* __restrict__ Wa_i,
            const int* __restrict__ uids, const int* __restrict__ iids, int B)
{
    int gw = (blockIdx.x * blockDim.x + threadIdx.x) >> 5;
    int lane = threadIdx.x & 31;
    if (gw >= 2 * B) return;
    int side = gw >= B ? 1 : 0;
    int b = side ? gw - B : gw;
    int id = side ? iids[b] : uids[b];
    const float* tab = side ? itab : utab;
    const float* wa = (side ? Wa_i : Wa_u) + EMB;   // dst half of attention vector

    float2 v = *(const float2*)(tab + (size_t)id * EMB + 2 * lane);
    float p = v.x * wa[2 * lane] + v.y * wa[2 * lane + 1];
    #pragma unroll
    for (int o = 16; o; o >>= 1) p += __shfl_xor_sync(0xffffffffu, p, o);

    *(float2*)(&g_hacc[side][(size_t)id * EMB + 2 * lane]) = make_float2(0.f, 0.f);
    if (lane == 0) {
        g_ds[side][id] = make_float2(p, 0.f);
        g_flag[side][id] = 1;
    }
}

// ---------------------------------------------------------------------------
// K2: single fused edge pass (filter + score + exp + weighted scatter).
// 32 edges per warp; flagged edges (~8%) processed warp-cooperatively.
// No segment-max subtraction: logit std ~0.1, constant factor cancels in alpha.
// Scatter uses red.global.add.v2.f32 (sm_90+) -> 32 REDs/edge instead of 64.
// ---------------------------------------------------------------------------
__global__ void __launch_bounds__(256)
edge_kernel(const float* __restrict__ utab, const float* __restrict__ itab,
            const float* __restrict__ Wa_u, const float* __restrict__ Wa_i,
            const int* __restrict__ src_iu, const int* __restrict__ dst_iu,
            const int* __restrict__ src_ui, const int* __restrict__ dst_ui,
            int E)
{
    int side = blockIdx.y;
    const float* stab = side ? utab : itab;         // source-node feature table
    const float* wa = side ? Wa_i : Wa_u;           // src half [0:64)
    const int* src = side ? src_ui : src_iu;
    const int* dst = side ? dst_ui : dst_iu;
    const unsigned char* flag = g_flag[side];

    int lane = threadIdx.x & 31;
    float wx = wa[2 * lane], wy = wa[2 * lane + 1];

    int warp = (blockIdx.x * blockDim.x + threadIdx.x) >> 5;
    int idx = warp * 32 + lane;

    int d = 0, s = 0, f = 0;
    if (idx < E) {
        d = dst[idx];
        f = flag[d];
        s = src[idx];
    }
    unsigned m = __ballot_sync(0xffffffffu, f);

    while (m) {
        int j = __ffs(m) - 1; m &= m - 1;
        int ds = __shfl_sync(0xffffffffu, d, j);
        int ss = __shfl_sync(0xffffffffu, s, j);

        // Warp-cooperative gather of the 64-float source row (256B, coalesced).
        float2 v = *(const float2*)(stab + (size_t)ss * EMB + 2 * lane);
        float p = v.x * wx + v.y * wy;
        #pragma unroll
        for (int o = 16; o; o >>= 1) p += __shfl_xor_sync(0xffffffffu, p, o);

        float e = p + g_ds[side][ds].x;
        e = e >= 0.f ? e : 0.01f * e;          // leaky_relu(., 0.01)
        float ex = __expf(e);

        if (lane == 0) atomicAdd(&g_ds[side][ds].y, ex);
        float* hp = &g_hacc[side][(size_t)ds * EMB + 2 * lane];
        asm volatile("red.global.add.v2.f32 [%0], {%1, %2};"
                     :: "l"(hp), "f"(v.x * ex), "f"(v.y * ex) : "memory");
    }
}

// ---------------------------------------------------------------------------
// K3a: z-half computation with 4x4 register tiling.
// grid (B/64, side, half). half 0: relu(Ws@x+bs) -> z[:, :64]
//                          half 1: relu(Wn@h+bn) -> z[:, 64:]
// Block: 256 threads as (tx 16, ty 16); each thread: 4 rows x 4 cols.
// Per k: 1 LDS.128 (weights) + 4 broadcast LDS (rows) for 16 FFMA.
// ---------------------------------------------------------------------------
__global__ void __launch_bounds__(256)
mlp1_kernel(const float* __restrict__ utab, const float* __restrict__ itab,
            const float* __restrict__ Ws_u, const float* __restrict__ bs_u,
            const float* __restrict__ Ws_i, const float* __restrict__ bs_i,
            const float* __restrict__ Wn_u, const float* __restrict__ bn_u,
            const float* __restrict__ Wn_i, const float* __restrict__ bn_i,
            const int* __restrict__ uids, const int* __restrict__ iids, int B)
{
    int side = blockIdx.y, half = blockIdx.z;
    const float* tab = side ? itab : utab;
    const float* W = half ? (side ? Wn_i : Wn_u) : (side ? Ws_i : Ws_u);
    const float* bias = half ? (side ? bn_i : bn_u) : (side ? bs_i : bs_u);
    const int* ids = side ? iids : uids;

    __shared__ float WT[64 * 68];    // WT[k][out], pad 68 (float4-aligned)
    __shared__ float vec[64 * 68];   // vec[row][k]
    __shared__ int   ids_s[64];
    __shared__ float rden_s[64];

    int tid = threadIdx.x;
    if (tid < 64) {
        int b = blockIdx.x * 64 + tid; if (b >= B) b = B - 1;
        int id = ids[b];
        ids_s[tid] = id;
        if (half) {
            float den = g_ds[side][id].y;
            rden_s[tid] = den > 0.f ? 1.f / den : 0.f;   // empty segment -> h = 0
        }
    }
    for (int t = tid; t < 4096; t += 256) {              // transpose W into smem
        int o = t >> 6, k = t & 63;
        WT[k * 68 + o] = W[t];
    }
    __syncthreads();
    for (int t = tid; t < 1024; t += 256) {              // gather input rows (float4)
        int row = t >> 4, k0 = (t & 15) * 4;
        int id = ids_s[row];
        const float* sp = half ? &g_hacc[side][(size_t)id * EMB + k0]
                               : &tab[(size_t)id * EMB + k0];
        float4 v = *(const float4*)sp;
        if (half) { float r = rden_s[row]; v.x *= r; v.y *= r; v.z *= r; v.w *= r; }
        *(float4*)&vec[row * 68 + k0] = v;
    }
    __syncthreads();

    int tx = tid & 15, ty = tid >> 4;
    float acc[4][4] = {};
    #pragma unroll 8
    for (int k = 0; k < 64; k++) {
        float4 w = *(const float4*)&WT[k * 68 + 4 * tx];
        #pragma unroll
        for (int c = 0; c < 4; c++) {
            float a = vec[(4 * ty + c) * 68 + k];
            acc[c][0] += a * w.x; acc[c][1] += a * w.y;
            acc[c][2] += a * w.z; acc[c][3] += a * w.w;
        }
    }

    float4 b4 = *(const float4*)&bias[4 * tx];
    #pragma unroll
    for (int c = 0; c < 4; c++) {
        int b = blockIdx.x * 64 + 4 * ty + c;
        if (b >= B) continue;
        float4 o;
        o.x = fmaxf(acc[c][0] + b4.x, 0.f);
        o.y = fmaxf(acc[c][1] + b4.y, 0.f);
        o.z = fmaxf(acc[c][2] + b4.z, 0.f);
        o.w = fmaxf(acc[c][3] + b4.w, 0.f);
        *(float4*)&g_z[side][(size_t)b * 2 * EMB + half * EMB + 4 * tx] = o;
    }
}

// ---------------------------------------------------------------------------
// K3b: out[:, side*64 + :] = relu(Wfc @ z), k=128 in two 64-wide smem chunks.
// Same 4x4 register tiling; accumulators persist across chunks.
// ---------------------------------------------------------------------------
__global__ void __launch_bounds__(256)
mlp2_kernel(const float* __restrict__ Wfc_u, const float* __restrict__ Wfc_i,
            float* __restrict__ out, int B)
{
    int side = blockIdx.y;
    const float* W = side ? Wfc_i : Wfc_u;   // [64][128] row-major

    __shared__ float WT[64 * 68];    // chunk: WT[k][out]
    __shared__ float zt[64 * 68];    // chunk: zt[row][k]

    int tid = threadIdx.x;
    int tx = tid & 15, ty = tid >> 4;
    float acc[4][4] = {};

    for (int kc = 0; kc < 2; kc++) {
        __syncthreads();
        for (int t = tid; t < 4096; t += 256) {
            int o = t >> 6, k = t & 63;
            WT[k * 68 + o] = W[o * 128 + kc * 64 + k];
        }
        for (int t = tid; t < 1024; t += 256) {
            int row = t >> 4, k0 = (t & 15) * 4;
            int b = blockIdx.x * 64 + row; if (b >= B) b = B - 1;
            *(float4*)&zt[row * 68 + k0] =
                *(const float4*)&g_z[side][(size_t)b * 2 * EMB + kc * 64 + k0];
        }
        __syncthreads();

        #pragma unroll 8
        for (int k = 0; k < 64; k++) {
            float4 w = *(const float4*)&WT[k * 68 + 4 * tx];
            #pragma unroll
            for (int c = 0; c < 4; c++) {
                float a = zt[(4 * ty + c) * 68 + k];
                acc[c][0] += a * w.x; acc[c][1] += a * w.y;
                acc[c][2] += a * w.z; acc[c][3] += a * w.w;
            }
        }
    }

    #pragma unroll
    for (int c = 0; c < 4; c++) {
        int b = blockIdx.x * 64 + 4 * ty + c;
        if (b >= B) continue;
        float4 o;
        o.x = fmaxf(acc[c][0], 0.f);
        o.y = fmaxf(acc[c][1], 0.f);
        o.z = fmaxf(acc[c][2], 0.f);
        o.w = fmaxf(acc[c][3], 0.f);
        *(float4*)&out[(size_t)b * 2 * EMB + side * EMB + 4 * tx] = o;
    }
}

// ---------------------------------------------------------------------------
extern "C" void kernel_launch(void* const* d_in, const int* in_sizes, int n_in,
                              void* d_out, int out_size)
{
    const float* user_emb = (const float*)d_in[0];
    const float* item_emb = (const float*)d_in[1];
    const float* Wa_u = (const float*)d_in[2];
    const float* Wa_i = (const float*)d_in[3];
    const float* Wfc_u = (const float*)d_in[4];
    const float* Wfc_i = (const float*)d_in[5];
    const float* Ws_u = (const float*)d_in[6];
    const float* bs_u = (const float*)d_in[7];
    const float* Ws_i = (const float*)d_in[8];
    const float* bs_i = (const float*)d_in[9];
    const float* Wn_u = (const float*)d_in[10];
    const float* bn_u = (const float*)d_in[11];
    const float* Wn_i = (const float*)d_in[12];
    const float* bn_i = (const float*)d_in[13];
    const int* u      = (const int*)d_in[14];
    const int* ii     = (const int*)d_in[15];
    const int* src_iu = (const int*)d_in[16];
    const int* dst_iu = (const int*)d_in[17];
    const int* src_ui = (const int*)d_in[18];
    const int* dst_ui = (const int*)d_in[19];
    int B = in_sizes[14];
    int E = in_sizes[16];
    float* out = (float*)d_out;

    {   // K1: mark + zero + dst scores. One warp per (side, b).
        int threads = 256;
        int blocks = (2 * B * 32 + threads - 1) / threads;
        prep_kernel<<<blocks, threads>>>(user_emb, item_emb, Wa_u, Wa_i, u, ii, B);
    }
    {   // K2: fused filtered edge pass, both sides concurrent via gridDim.y.
        int threads = 256;
        int blocks = (E + 8 * 32 - 1) / (8 * 32);
        dim3 g(blocks, 2);
        edge_kernel<<<g, threads>>>(user_emb, item_emb, Wa_u, Wa_i,
                                    src_iu, dst_iu, src_ui, dst_ui, E);
    }
    {   // K3: register-tiled dense MLPs.
        dim3 g1((B + 63) / 64, 2, 2);
        mlp1_kernel<<<g1, 256>>>(user_emb, item_emb, Ws_u, bs_u, Ws_i, bs_i,
                                 Wn_u, bn_u, Wn_i, bn_i, u, ii, B);
        dim3 g2((B + 63) / 64, 2);
        mlp2_kernel<<<g2, 256>>>(Wfc_u, Wfc_i, out, B);
    }
}